// round 2
// baseline (speedup 1.0000x reference)
#include <cuda_runtime.h>

#define N_NODES 50000
#define N_EDGES 800000
#define C_IN    128
#define HEADS   4
#define C_HEAD  32
#define C_OUT   128
#define NEG_SLOPE 0.2f

// ---------------- scratch (static device globals; no allocation) ----------------
__device__ float    g_xl[N_NODES * C_OUT];        // projected features [N,128]
__device__ float    g_asrc[N_NODES * HEADS];      // per-node src attention logit
__device__ float    g_adst[N_NODES * HEADS];      // per-node dst attention logit
__device__ unsigned g_menc[N_NODES * HEADS];      // segment max, order-preserving uint encoding
__device__ float    g_denom[N_NODES * HEADS];     // softmax denominator

// order-preserving float<->uint encoding (monotone; works for atomicMax on unsigned)
__device__ __forceinline__ unsigned enc_f(float f) {
    unsigned u = __float_as_uint(f);
    return (u & 0x80000000u) ? ~u : (u | 0x80000000u);
}
__device__ __forceinline__ float dec_f(unsigned u) {
    return (u & 0x80000000u) ? __uint_as_float(u ^ 0x80000000u) : __uint_as_float(~u);
}
__device__ __forceinline__ float leaky(float v) {
    return v > 0.0f ? v : NEG_SLOPE * v;
}

// ---------------- K1: xl = x @ W  (M=50000, N=128, K=128 fp32) ----------------
__global__ __launch_bounds__(256) void gemm128(const float* __restrict__ X,
                                               const float* __restrict__ W) {
    __shared__ float As[16][132];   // transposed A tile [k][row], padded
    __shared__ float Bs[16][128];   // B tile [k][col]
    const int tid  = threadIdx.x;
    const int row0 = blockIdx.x * 128;
    const int tx = tid & 15, ty = tid >> 4;

    float acc[8][8];
#pragma unroll
    for (int i = 0; i < 8; i++)
#pragma unroll
        for (int j = 0; j < 8; j++) acc[i][j] = 0.0f;

    const int arow = tid >> 1;          // 0..127
    const int akc  = (tid & 1) * 8;     // 0 or 8
    const int brow = tid >> 4;          // 0..15
    const int bcol = (tid & 15) * 8;    // 0..120
    const int grow = row0 + arow;
    const bool avalid = grow < N_NODES;

    for (int k0 = 0; k0 < C_IN; k0 += 16) {
        float4 a0 = make_float4(0, 0, 0, 0), a1 = make_float4(0, 0, 0, 0);
        if (avalid) {
            a0 = *(const float4*)(X + (size_t)grow * C_IN + k0 + akc);
            a1 = *(const float4*)(X + (size_t)grow * C_IN + k0 + akc + 4);
        }
        float4 b0 = *(const float4*)(W + (size_t)(k0 + brow) * C_OUT + bcol);
        float4 b1 = *(const float4*)(W + (size_t)(k0 + brow) * C_OUT + bcol + 4);
        __syncthreads();
        As[akc + 0][arow] = a0.x; As[akc + 1][arow] = a0.y;
        As[akc + 2][arow] = a0.z; As[akc + 3][arow] = a0.w;
        As[akc + 4][arow] = a1.x; As[akc + 5][arow] = a1.y;
        As[akc + 6][arow] = a1.z; As[akc + 7][arow] = a1.w;
        *(float4*)&Bs[brow][bcol]     = b0;
        *(float4*)&Bs[brow][bcol + 4] = b1;
        __syncthreads();
#pragma unroll
        for (int k = 0; k < 16; k++) {
            float a[8], b[8];
            *(float4*)(a)     = *(const float4*)&As[k][ty * 8];
            *(float4*)(a + 4) = *(const float4*)&As[k][ty * 8 + 4];
            *(float4*)(b)     = *(const float4*)&Bs[k][tx * 8];
            *(float4*)(b + 4) = *(const float4*)&Bs[k][tx * 8 + 4];
#pragma unroll
            for (int i = 0; i < 8; i++)
#pragma unroll
                for (int j = 0; j < 8; j++) acc[i][j] = fmaf(a[i], b[j], acc[i][j]);
        }
    }
#pragma unroll
    for (int i = 0; i < 8; i++) {
        int r = row0 + ty * 8 + i;
        if (r < N_NODES) {
            *(float4*)(g_xl + (size_t)r * C_OUT + tx * 8)     = make_float4(acc[i][0], acc[i][1], acc[i][2], acc[i][3]);
            *(float4*)(g_xl + (size_t)r * C_OUT + tx * 8 + 4) = make_float4(acc[i][4], acc[i][5], acc[i][6], acc[i][7]);
        }
    }
}

// ---------------- K2: per-(node,head) attention dots + self-loop max init ----------------
__global__ void node_attn(const float* __restrict__ att_src,
                          const float* __restrict__ att_dst) {
    int t = blockIdx.x * blockDim.x + threadIdx.x;   // n*HEADS + h
    if (t >= N_NODES * HEADS) return;
    int n = t >> 2, h = t & 3;
    const float4* row = (const float4*)(g_xl + (size_t)n * C_OUT + h * C_HEAD);
    const float4* as  = (const float4*)(att_src + h * C_HEAD);
    const float4* ad  = (const float4*)(att_dst + h * C_HEAD);
    float s = 0.0f, d = 0.0f;
#pragma unroll
    for (int i = 0; i < 8; i++) {
        float4 v = row[i], a = as[i], b = ad[i];
        s += v.x * a.x + v.y * a.y + v.z * a.z + v.w * a.w;
        d += v.x * b.x + v.y * b.y + v.z * b.z + v.w * b.w;
    }
    g_asrc[t] = s;
    g_adst[t] = d;
    g_menc[t] = enc_f(leaky(s + d));   // self-loop initializes the segment max
}

// ---------------- K3: edge segment max ----------------
__global__ void edge_max(const int* __restrict__ ei) {
    int e = blockIdx.x * blockDim.x + threadIdx.x;
    if (e >= N_EDGES) return;
    int s = ei[e];
    int d = ei[N_EDGES + e];
    if (s == d) return;   // self-edges dropped by reference
    float4 as = *(const float4*)(g_asrc + s * 4);
    float4 ad = *(const float4*)(g_adst + d * 4);
    atomicMax(&g_menc[d * 4 + 0], enc_f(leaky(as.x + ad.x)));
    atomicMax(&g_menc[d * 4 + 1], enc_f(leaky(as.y + ad.y)));
    atomicMax(&g_menc[d * 4 + 2], enc_f(leaky(as.z + ad.z)));
    atomicMax(&g_menc[d * 4 + 3], enc_f(leaky(as.w + ad.w)));
}

// ---------------- K4a: denominator init (self-loop term) ----------------
__global__ void denom_init() {
    int t = blockIdx.x * blockDim.x + threadIdx.x;
    if (t >= N_NODES * HEADS) return;
    float m = dec_f(g_menc[t]);
    float e = leaky(g_asrc[t] + g_adst[t]);
    g_denom[t] = __expf(e - m);
}

// ---------------- K4b: denominator edge accumulation ----------------
__global__ void denom_edges(const int* __restrict__ ei) {
    int e = blockIdx.x * blockDim.x + threadIdx.x;
    if (e >= N_EDGES) return;
    int s = ei[e];
    int d = ei[N_EDGES + e];
    if (s == d) return;
    float4 as = *(const float4*)(g_asrc + s * 4);
    float4 ad = *(const float4*)(g_adst + d * 4);
#pragma unroll
    for (int h = 0; h < 4; h++) {
        float av = (h == 0) ? as.x : (h == 1) ? as.y : (h == 2) ? as.z : as.w;
        float bv = (h == 0) ? ad.x : (h == 1) ? ad.y : (h == 2) ? ad.z : ad.w;
        float ev = leaky(av + bv);
        float m  = dec_f(g_menc[d * 4 + h]);
        atomicAdd(&g_denom[d * 4 + h], __expf(ev - m));
    }
}

// ---------------- K5a: output init = 0.5*(bias + alpha_self * xl) ----------------
__global__ void out_init(const float* __restrict__ bias, float* __restrict__ out) {
    int t = blockIdx.x * blockDim.x + threadIdx.x;   // n*32 + c4  (4 floats per thread)
    if (t >= N_NODES * 32) return;
    int n  = t >> 5;
    int c4 = t & 31;
    int c  = c4 * 4;
    int h  = c >> 5;   // c / C_HEAD
    int th = n * 4 + h;
    float m = dec_f(g_menc[th]);
    float e = leaky(g_asrc[th] + g_adst[th]);
    float alpha = 0.5f * __expf(e - m) / g_denom[th];
    float4 v = *(const float4*)(g_xl + (size_t)n * C_OUT + c);
    float4 b = *(const float4*)(bias + c);
    float4 r;
    r.x = 0.5f * b.x + alpha * v.x;
    r.y = 0.5f * b.y + alpha * v.y;
    r.z = 0.5f * b.z + alpha * v.z;
    r.w = 0.5f * b.w + alpha * v.w;
    *(float4*)(out + (size_t)n * C_OUT + c) = r;
}

// ---------------- K5b: edge aggregation (warp per edge, red.v4) ----------------
__global__ __launch_bounds__(256) void edge_aggr(const int* __restrict__ ei,
                                                 float* __restrict__ out) {
    int warp = (blockIdx.x * blockDim.x + threadIdx.x) >> 5;
    int lane = threadIdx.x & 31;
    if (warp >= N_EDGES) return;
    int s = ei[warp];
    int d = ei[N_EDGES + warp];
    if (s == d) return;
    int h  = lane >> 3;                 // 8 lanes per head (8*4 = 32 channels)
    int th = d * 4 + h;
    float e = leaky(g_asrc[s * 4 + h] + g_adst[th]);
    float m = dec_f(g_menc[th]);
    float alpha = 0.5f * __expf(e - m) / g_denom[th];
    float4 v = *(const float4*)(g_xl + (size_t)s * C_OUT + lane * 4);
    float* dst = out + (size_t)d * C_OUT + lane * 4;
    asm volatile("red.global.add.v4.f32 [%0], {%1, %2, %3, %4};" ::
                 "l"(dst), "f"(alpha * v.x), "f"(alpha * v.y),
                 "f"(alpha * v.z), "f"(alpha * v.w)
                 : "memory");
}

// ---------------- launch ----------------
extern "C" void kernel_launch(void* const* d_in, const int* in_sizes, int n_in,
                              void* d_out, int out_size) {
    const float* x   = (const float*)d_in[0];
    const int*   ei  = (const int*)d_in[1];
    const float* W   = (const float*)d_in[2];
    const float* as  = (const float*)d_in[3];
    const float* ad  = (const float*)d_in[4];
    const float* bs  = (const float*)d_in[5];
    float*       out = (float*)d_out;

    gemm128<<<(N_NODES + 127) / 128, 256>>>(x, W);
    node_attn<<<(N_NODES * HEADS + 255) / 256, 256>>>(as, ad);
    edge_max<<<(N_EDGES + 255) / 256, 256>>>(ei);
    denom_init<<<(N_NODES * HEADS + 255) / 256, 256>>>();
    denom_edges<<<(N_EDGES + 255) / 256, 256>>>(ei);
    out_init<<<(N_NODES * 32 + 255) / 256, 256>>>(bs, out);
    edge_aggr<<<(N_EDGES * 32 + 255) / 256, 256>>>(ei, out);
}

// round 3
// speedup vs baseline: 1.1610x; 1.1610x over previous
#include <cuda_runtime.h>

#define N_NODES 50000
#define N_EDGES 800000
#define C_IN    128
#define HEADS   4
#define C_HEAD  32
#define C_OUT   128
#define NEG_SLOPE 0.2f

// ---------------- scratch (static device globals; no allocation) ----------------
__device__ float g_xl[N_NODES * C_OUT];       // projected features [N,128]
__device__ float g_accum[N_NODES * C_OUT];    // unnormalized aggregation
__device__ float g_asrc[N_NODES * HEADS];     // per-node src attention logit
__device__ float g_adst[N_NODES * HEADS];     // per-node dst attention logit
__device__ float g_denom[N_NODES * HEADS];    // softmax denominator (unnormalized)

__device__ __forceinline__ float leaky(float v) {
    return v > 0.0f ? v : NEG_SLOPE * v;
}

// ---------------- K1: xl = x @ W  (M=50000, N=128, K=128 fp32) ----------------
__global__ __launch_bounds__(256) void gemm128(const float* __restrict__ X,
                                               const float* __restrict__ W) {
    __shared__ float As[16][132];   // transposed A tile [k][row], padded
    __shared__ float Bs[16][128];   // B tile [k][col]
    const int tid  = threadIdx.x;
    const int row0 = blockIdx.x * 128;
    const int tx = tid & 15, ty = tid >> 4;

    float acc[8][8];
#pragma unroll
    for (int i = 0; i < 8; i++)
#pragma unroll
        for (int j = 0; j < 8; j++) acc[i][j] = 0.0f;

    const int arow = tid >> 1;          // 0..127
    const int akc  = (tid & 1) * 8;     // 0 or 8
    const int brow = tid >> 4;          // 0..15
    const int bcol = (tid & 15) * 8;    // 0..120
    const int grow = row0 + arow;
    const bool avalid = grow < N_NODES;

    for (int k0 = 0; k0 < C_IN; k0 += 16) {
        float4 a0 = make_float4(0, 0, 0, 0), a1 = make_float4(0, 0, 0, 0);
        if (avalid) {
            a0 = *(const float4*)(X + (size_t)grow * C_IN + k0 + akc);
            a1 = *(const float4*)(X + (size_t)grow * C_IN + k0 + akc + 4);
        }
        float4 b0 = *(const float4*)(W + (size_t)(k0 + brow) * C_OUT + bcol);
        float4 b1 = *(const float4*)(W + (size_t)(k0 + brow) * C_OUT + bcol + 4);
        __syncthreads();
        As[akc + 0][arow] = a0.x; As[akc + 1][arow] = a0.y;
        As[akc + 2][arow] = a0.z; As[akc + 3][arow] = a0.w;
        As[akc + 4][arow] = a1.x; As[akc + 5][arow] = a1.y;
        As[akc + 6][arow] = a1.z; As[akc + 7][arow] = a1.w;
        *(float4*)&Bs[brow][bcol]     = b0;
        *(float4*)&Bs[brow][bcol + 4] = b1;
        __syncthreads();
#pragma unroll
        for (int k = 0; k < 16; k++) {
            float a[8], b[8];
            *(float4*)(a)     = *(const float4*)&As[k][ty * 8];
            *(float4*)(a + 4) = *(const float4*)&As[k][ty * 8 + 4];
            *(float4*)(b)     = *(const float4*)&Bs[k][tx * 8];
            *(float4*)(b + 4) = *(const float4*)&Bs[k][tx * 8 + 4];
#pragma unroll
            for (int i = 0; i < 8; i++)
#pragma unroll
                for (int j = 0; j < 8; j++) acc[i][j] = fmaf(a[i], b[j], acc[i][j]);
        }
    }
#pragma unroll
    for (int i = 0; i < 8; i++) {
        int r = row0 + ty * 8 + i;
        if (r < N_NODES) {
            *(float4*)(g_xl + (size_t)r * C_OUT + tx * 8)     = make_float4(acc[i][0], acc[i][1], acc[i][2], acc[i][3]);
            *(float4*)(g_xl + (size_t)r * C_OUT + tx * 8 + 4) = make_float4(acc[i][4], acc[i][5], acc[i][6], acc[i][7]);
        }
    }
}

// ---------------- K2: per-(node,head) attention dots + self-loop denom init ----------------
__global__ void node_attn(const float* __restrict__ att_src,
                          const float* __restrict__ att_dst) {
    int t = blockIdx.x * blockDim.x + threadIdx.x;   // n*HEADS + h
    if (t >= N_NODES * HEADS) return;
    int n = t >> 2, h = t & 3;
    const float4* row = (const float4*)(g_xl + (size_t)n * C_OUT + h * C_HEAD);
    const float4* as  = (const float4*)(att_src + h * C_HEAD);
    const float4* ad  = (const float4*)(att_dst + h * C_HEAD);
    float s = 0.0f, d = 0.0f;
#pragma unroll
    for (int i = 0; i < 8; i++) {
        float4 v = row[i], a = as[i], b = ad[i];
        s += v.x * a.x + v.y * a.y + v.z * a.z + v.w * a.w;
        d += v.x * b.x + v.y * b.y + v.z * b.z + v.w * b.w;
    }
    g_asrc[t] = s;
    g_adst[t] = d;
    g_denom[t] = __expf(leaky(s + d));   // self-loop term (no max subtraction needed)
}

// ---------------- K3: accum init = w_self * xl ----------------
__global__ void init_accum() {
    int t = blockIdx.x * blockDim.x + threadIdx.x;   // n*32 + c4
    if (t >= N_NODES * 32) return;
    int n  = t >> 5;
    int c4 = t & 31;
    int c  = c4 * 4;
    int h  = c >> 5;
    float w = g_denom[n * 4 + h];        // currently holds only the self term
    float4 v = *(const float4*)(g_xl + (size_t)n * C_OUT + c);
    float4 r;
    r.x = w * v.x; r.y = w * v.y; r.z = w * v.z; r.w = w * v.w;
    *(float4*)(g_accum + (size_t)n * C_OUT + c) = r;
}

// ---------------- K4: fused edge pass (denominator + aggregation) ----------------
__global__ __launch_bounds__(256) void edge_aggr(const int* __restrict__ ei) {
    int warp = (blockIdx.x * blockDim.x + threadIdx.x) >> 5;
    int lane = threadIdx.x & 31;
    if (warp >= N_EDGES) return;
    int s = __ldg(ei + warp);
    int d = __ldg(ei + N_EDGES + warp);
    if (s == d) return;
    int h  = lane >> 3;                 // 8 lanes per head (8*4 = 32 channels)
    int th = d * 4 + h;
    float w = __expf(leaky(g_asrc[s * 4 + h] + g_adst[th]));
    if ((lane & 7) == 0) atomicAdd(&g_denom[th], w);
    float4 v = *(const float4*)(g_xl + (size_t)s * C_OUT + lane * 4);
    float* dst = g_accum + (size_t)d * C_OUT + lane * 4;
    asm volatile("red.global.add.v4.f32 [%0], {%1, %2, %3, %4};" ::
                 "l"(dst), "f"(w * v.x), "f"(w * v.y),
                 "f"(w * v.z), "f"(w * v.w)
                 : "memory");
}

// ---------------- K5: finalize out = 0.5*(bias + accum/denom) ----------------
__global__ void finalize(const float* __restrict__ bias, float* __restrict__ out) {
    int t = blockIdx.x * blockDim.x + threadIdx.x;   // n*32 + c4
    if (t >= N_NODES * 32) return;
    int n  = t >> 5;
    int c4 = t & 31;
    int c  = c4 * 4;
    int h  = c >> 5;
    float inv = 0.5f / g_denom[n * 4 + h];
    float4 a = *(const float4*)(g_accum + (size_t)n * C_OUT + c);
    float4 b = *(const float4*)(bias + c);
    float4 r;
    r.x = 0.5f * b.x + inv * a.x;
    r.y = 0.5f * b.y + inv * a.y;
    r.z = 0.5f * b.z + inv * a.z;
    r.w = 0.5f * b.w + inv * a.w;
    *(float4*)(out + (size_t)n * C_OUT + c) = r;
}

// ---------------- launch ----------------
extern "C" void kernel_launch(void* const* d_in, const int* in_sizes, int n_in,
                              void* d_out, int out_size) {
    const float* x   = (const float*)d_in[0];
    const int*   ei  = (const int*)d_in[1];
    const float* W   = (const float*)d_in[2];
    const float* as  = (const float*)d_in[3];
    const float* ad  = (const float*)d_in[4];
    const float* bs  = (const float*)d_in[5];
    float*       out = (float*)d_out;

    gemm128<<<(N_NODES + 127) / 128, 256>>>(x, W);
    node_attn<<<(N_NODES * HEADS + 255) / 256, 256>>>(as, ad);
    init_accum<<<(N_NODES * 32 + 255) / 256, 256>>>();
    edge_aggr<<<(N_EDGES * 32 + 255) / 256, 256>>>(ei);
    finalize<<<(N_NODES * 32 + 255) / 256, 256>>>(bs, out);
}